// round 1
// baseline (speedup 1.0000x reference)
#include <cuda_runtime.h>
#include <cuda_bf16.h>
#include <mma.h>
#include <math.h>

using namespace nvcuda;

// ---------------- problem constants ----------------
constexpr int B_   = 4;
constexpr int S_   = 4096;
constexpr int D_   = 1024;   // token dim
constexpr int H_   = 1024;   // hidden dim
constexpr int WIN  = 256;
constexpr int STRIDE_ = 128;
constexpr int GLOB = 16;
constexpr float EPS = 1e-5f;
constexpr float SCALE = 1.0f / 32.0f;  // 1/sqrt(1024)

constexpr int ROWS = B_ * S_;          // 16384
constexpr size_t NELEM = (size_t)ROWS * D_;  // 16,777,216

// ---------------- scratch (static device globals; allocation-free) ----------
__device__ __nv_bfloat16 g_x[NELEM];       // LN1 output (bf16)
__device__ __nv_bfloat16 g_wq[D_ * H_];
__device__ __nv_bfloat16 g_wk[D_ * H_];
__device__ __nv_bfloat16 g_wv[D_ * D_];
__device__ __nv_bfloat16 g_wo[D_ * D_];
__device__ float g_Q[NELEM];
__device__ float g_K[NELEM];
__device__ float g_V[NELEM];
__device__ __nv_bfloat16 g_attn[NELEM];    // attention output (bf16)
__device__ float g_o[NELEM];               // attn @ Wo (fp32)

// ---------------- weight conversion ----------------
__global__ void cvt_kernel(const float* __restrict__ w, __nv_bfloat16* __restrict__ o, int n) {
    int i = blockIdx.x * blockDim.x + threadIdx.x;
    if (i < n) o[i] = __float2bfloat16(w[i]);
}

// ---------------- LayerNorm 1: tokens -> bf16 x ----------------
__global__ void ln1_kernel(const float* __restrict__ tokens,
                           const float* __restrict__ g, const float* __restrict__ beta,
                           __nv_bfloat16* __restrict__ out) {
    int row = blockIdx.x;
    int tid = threadIdx.x;
    const float* r = tokens + (size_t)row * D_;
    float v[4], s = 0.f, ss = 0.f;
#pragma unroll
    for (int c = 0; c < 4; c++) {
        v[c] = r[tid + 256 * c];
        s += v[c]; ss += v[c] * v[c];
    }
    __shared__ float rs[256], rss[256];
    rs[tid] = s; rss[tid] = ss;
    __syncthreads();
    for (int o = 128; o > 0; o >>= 1) {
        if (tid < o) { rs[tid] += rs[tid + o]; rss[tid] += rss[tid + o]; }
        __syncthreads();
    }
    float mean = rs[0] * (1.0f / D_);
    float var  = rss[0] * (1.0f / D_) - mean * mean;
    float inv  = rsqrtf(var + EPS);
#pragma unroll
    for (int c = 0; c < 4; c++) {
        int idx = tid + 256 * c;
        out[(size_t)row * D_ + idx] =
            __float2bfloat16((v[c] - mean) * inv * g[idx] + beta[idx]);
    }
}

// ---------------- LayerNorm 2: tokens + 0.1*o -> fp32 out ----------------
__global__ void ln2_kernel(const float* __restrict__ tokens,
                           const float* __restrict__ oin,
                           const float* __restrict__ g, const float* __restrict__ beta,
                           float* __restrict__ out) {
    int row = blockIdx.x;
    int tid = threadIdx.x;
    const float* r  = tokens + (size_t)row * D_;
    const float* ro = oin    + (size_t)row * D_;
    float v[4], s = 0.f, ss = 0.f;
#pragma unroll
    for (int c = 0; c < 4; c++) {
        int idx = tid + 256 * c;
        v[c] = r[idx] + 0.1f * ro[idx];
        s += v[c]; ss += v[c] * v[c];
    }
    __shared__ float rs[256], rss[256];
    rs[tid] = s; rss[tid] = ss;
    __syncthreads();
    for (int o = 128; o > 0; o >>= 1) {
        if (tid < o) { rs[tid] += rs[tid + o]; rss[tid] += rss[tid + o]; }
        __syncthreads();
    }
    float mean = rs[0] * (1.0f / D_);
    float var  = rss[0] * (1.0f / D_) - mean * mean;
    float inv  = rsqrtf(var + EPS);
#pragma unroll
    for (int c = 0; c < 4; c++) {
        int idx = tid + 256 * c;
        out[(size_t)row * D_ + idx] = (v[c] - mean) * inv * g[idx] + beta[idx];
    }
}

// ---------------- wmma bf16 GEMM: C[M,1024] = A[M,1024] * B[1024,1024] -----
// blockIdx.z selects (B,C) pair (used for fused QKV; z=0 only for O proj).
constexpr int BM = 128, BN = 128, BK = 32;
constexpr int APAD_LD = 48;   // A smem leading dim (elems)
constexpr int BPAD_LD = 136;  // B smem leading dim (elems)

__global__ void gemm_kernel(const __nv_bfloat16* __restrict__ A,
                            const __nv_bfloat16* __restrict__ B0,
                            const __nv_bfloat16* __restrict__ B1,
                            const __nv_bfloat16* __restrict__ B2,
                            float* __restrict__ C0,
                            float* __restrict__ C1,
                            float* __restrict__ C2) {
    const __nv_bfloat16* Bm = (blockIdx.z == 0) ? B0 : (blockIdx.z == 1) ? B1 : B2;
    float* C = (blockIdx.z == 0) ? C0 : (blockIdx.z == 1) ? C1 : C2;

    __shared__ __align__(16) __nv_bfloat16 As[BM][APAD_LD];
    __shared__ __align__(16) __nv_bfloat16 Bs[BK][BPAD_LD];

    int m0 = blockIdx.y * BM;
    int n0 = blockIdx.x * BN;
    int tid = threadIdx.x;
    int wid = tid >> 5;
    int wm = wid & 3;          // 0..3 -> 32 rows each
    int wn = wid >> 2;         // 0..1 -> 64 cols each

    wmma::fragment<wmma::accumulator, 16, 16, 16, float> cf[2][4];
#pragma unroll
    for (int r = 0; r < 2; r++)
#pragma unroll
        for (int c = 0; c < 4; c++)
            wmma::fill_fragment(cf[r][c], 0.0f);

    for (int k0 = 0; k0 < 1024; k0 += BK) {
        // load A tile 128x32 (512 uint4)
#pragma unroll
        for (int r = 0; r < 2; r++) {
            int idx = tid + r * 256;
            int row = idx >> 2, c4 = idx & 3;
            *(uint4*)&As[row][c4 * 8] =
                *(const uint4*)&A[(size_t)(m0 + row) * 1024 + k0 + c4 * 8];
        }
        // load B tile 32x128 (512 uint4)
#pragma unroll
        for (int r = 0; r < 2; r++) {
            int idx = tid + r * 256;
            int row = idx >> 4, c4 = idx & 15;
            *(uint4*)&Bs[row][c4 * 8] =
                *(const uint4*)&Bm[(size_t)(k0 + row) * 1024 + n0 + c4 * 8];
        }
        __syncthreads();
#pragma unroll
        for (int kk = 0; kk < 2; kk++) {
            wmma::fragment<wmma::matrix_a, 16, 16, 16, __nv_bfloat16, wmma::row_major> af[2];
            wmma::fragment<wmma::matrix_b, 16, 16, 16, __nv_bfloat16, wmma::row_major> bf[4];
#pragma unroll
            for (int r = 0; r < 2; r++)
                wmma::load_matrix_sync(af[r], &As[wm * 32 + r * 16][kk * 16], APAD_LD);
#pragma unroll
            for (int c = 0; c < 4; c++)
                wmma::load_matrix_sync(bf[c], &Bs[kk * 16][wn * 64 + c * 16], BPAD_LD);
#pragma unroll
            for (int r = 0; r < 2; r++)
#pragma unroll
                for (int c = 0; c < 4; c++)
                    wmma::mma_sync(cf[r][c], af[r], bf[c], cf[r][c]);
        }
        __syncthreads();
    }
#pragma unroll
    for (int r = 0; r < 2; r++)
#pragma unroll
        for (int c = 0; c < 4; c++) {
            float* p = C + (size_t)(m0 + wm * 32 + r * 16) * 1024 + n0 + wn * 64 + c * 16;
            wmma::store_matrix_sync(p, cf[r][c], 1024, wmma::mem_row_major);
        }
}

// ---------------- sparse attention ----------------
// One block per (batch, 16-query tile). Union key list in smem; warp-per-key
// scores; per-query softmax; register-accumulated AV with warp-owned d-chunks.
constexpr int QT = 16;
constexpr int MAXU = 800;
constexpr size_t ATTN_SMEM =
    (size_t)QT * H_ * 4          // Qs
  + (size_t)QT * MAXU * 4        // scores
  + (size_t)MAXU * 4             // klist
  + 16;                          // counter

__global__ void attn_kernel(const float* __restrict__ Q,
                            const float* __restrict__ K,
                            const float* __restrict__ V,
                            __nv_bfloat16* __restrict__ attn) {
    extern __shared__ float sm[];
    float* Qs   = sm;                          // [QT][H_]
    float* sc   = Qs + QT * H_;                // [QT][MAXU]
    int*   klist = (int*)(sc + QT * MAXU);     // [MAXU]
    int*   cntp  = klist + MAXU;

    int b  = blockIdx.y;
    int i0 = blockIdx.x * QT;
    int tid = threadIdx.x;
    int lane = tid & 31;
    int wid  = tid >> 5;

    // load Q tile
    const float* Qbase = Q + ((size_t)b * S_ + i0) * H_;
    for (int idx = tid; idx < QT * H_; idx += 256) Qs[idx] = Qbase[idx];
    for (int idx = tid; idx < QT * MAXU; idx += 256) sc[idx] = -INFINITY;
    if (tid == 0) *cntp = 0;
    __syncthreads();

    // build union key list: window-union + global + strided residues of tile
    int imax   = i0 + QT - 1;
    int wstart = max(0, i0 - (WIN - 1));
    for (int j = tid; j <= imax; j += 256) {
        bool inc;
        if (j >= wstart)       inc = true;
        else if (j < GLOB)     inc = true;
        else {
            int u = ((j - i0) % STRIDE_ + STRIDE_) % STRIDE_;
            inc = (u < QT);
        }
        if (inc) { int p = atomicAdd(cntp, 1); klist[p] = j; }
    }
    __syncthreads();
    int cnt = *cntp;

    // scores: warp per key
    for (int ku = wid; ku < cnt; ku += 8) {
        int j = klist[ku];
        const float* Krow = K + ((size_t)b * S_ + j) * H_;
        float kr[32];
#pragma unroll
        for (int t = 0; t < 32; t++) kr[t] = Krow[lane + 32 * t];
#pragma unroll 1
        for (int q = 0; q < QT; q++) {
            int i = i0 + q;
            int dij = i - j;
            bool ok = (dij >= 0) && ((dij < WIN) || ((dij % STRIDE_) == 0) || (j < GLOB));
            if (!ok) continue;
            const float* Qr = Qs + q * H_;
            float p = 0.f;
#pragma unroll
            for (int t = 0; t < 32; t++) p += kr[t] * Qr[lane + 32 * t];
#pragma unroll
            for (int o = 16; o > 0; o >>= 1) p += __shfl_down_sync(0xffffffffu, p, o);
            if (lane == 0) sc[q * MAXU + ku] = p * SCALE;
        }
    }
    __syncthreads();

    // softmax: warp per query
    for (int q = wid; q < QT; q += 8) {
        float m = -INFINITY;
        for (int ku = lane; ku < cnt; ku += 32) m = fmaxf(m, sc[q * MAXU + ku]);
#pragma unroll
        for (int o = 16; o > 0; o >>= 1) m = fmaxf(m, __shfl_xor_sync(0xffffffffu, m, o));
        float s = 0.f;
        for (int ku = lane; ku < cnt; ku += 32) {
            float e = expf(sc[q * MAXU + ku] - m);
            sc[q * MAXU + ku] = e;
            s += e;
        }
#pragma unroll
        for (int o = 16; o > 0; o >>= 1) s += __shfl_xor_sync(0xffffffffu, s, o);
        float inv = 1.f / s;
        for (int ku = lane; ku < cnt; ku += 32) sc[q * MAXU + ku] *= inv;
    }
    __syncthreads();

    // AV: warp owns 128-wide d chunk; accumulate all queries in registers
    int d0 = wid * 128;
    float acc[QT][4];
#pragma unroll
    for (int q = 0; q < QT; q++)
#pragma unroll
        for (int c = 0; c < 4; c++) acc[q][c] = 0.f;

    for (int ku = 0; ku < cnt; ku++) {
        int j = klist[ku];
        const float* Vrow = V + ((size_t)b * S_ + j) * H_ + d0 + lane;
        float v0 = Vrow[0], v1 = Vrow[32], v2 = Vrow[64], v3 = Vrow[96];
#pragma unroll
        for (int q = 0; q < QT; q++) {
            float w = sc[q * MAXU + ku];
            if (w > 0.f) {
                acc[q][0] += w * v0;
                acc[q][1] += w * v1;
                acc[q][2] += w * v2;
                acc[q][3] += w * v3;
            }
        }
    }
#pragma unroll
    for (int q = 0; q < QT; q++) {
        __nv_bfloat16* orow = attn + ((size_t)b * S_ + i0 + q) * H_ + d0 + lane;
        orow[0]  = __float2bfloat16(acc[q][0]);
        orow[32] = __float2bfloat16(acc[q][1]);
        orow[64] = __float2bfloat16(acc[q][2]);
        orow[96] = __float2bfloat16(acc[q][3]);
    }
}

// ---------------- launch ----------------
extern "C" void kernel_launch(void* const* d_in, const int* in_sizes, int n_in,
                              void* d_out, int out_size) {
    const float* tokens = (const float*)d_in[0];
    const float* Wq = (const float*)d_in[1];
    const float* Wk = (const float*)d_in[2];
    const float* Wv = (const float*)d_in[3];
    const float* Wo = (const float*)d_in[4];
    const float* g1 = (const float*)d_in[5];
    const float* b1 = (const float*)d_in[6];
    const float* g2 = (const float*)d_in[7];
    const float* b2 = (const float*)d_in[8];
    float* out = (float*)d_out;

    __nv_bfloat16 *x, *wq, *wk, *wv, *wo, *attn;
    float *Qb, *Kb, *Vb, *ob;
    cudaGetSymbolAddress((void**)&x,    g_x);
    cudaGetSymbolAddress((void**)&wq,   g_wq);
    cudaGetSymbolAddress((void**)&wk,   g_wk);
    cudaGetSymbolAddress((void**)&wv,   g_wv);
    cudaGetSymbolAddress((void**)&wo,   g_wo);
    cudaGetSymbolAddress((void**)&Qb,   g_Q);
    cudaGetSymbolAddress((void**)&Kb,   g_K);
    cudaGetSymbolAddress((void**)&Vb,   g_V);
    cudaGetSymbolAddress((void**)&attn, g_attn);
    cudaGetSymbolAddress((void**)&ob,   g_o);

    int wn = D_ * H_;
    int cvtBlocks = (wn + 255) / 256;
    cvt_kernel<<<cvtBlocks, 256>>>(Wq, wq, wn);
    cvt_kernel<<<cvtBlocks, 256>>>(Wk, wk, wn);
    cvt_kernel<<<cvtBlocks, 256>>>(Wv, wv, wn);
    cvt_kernel<<<cvtBlocks, 256>>>(Wo, wo, wn);

    ln1_kernel<<<ROWS, 256>>>(tokens, g1, b1, x);

    // fused QKV projection
    gemm_kernel<<<dim3(H_ / BN, ROWS / BM, 3), 256>>>(x, wq, wk, wv, Qb, Kb, Vb);

    // sparse attention
    cudaFuncSetAttribute(attn_kernel, cudaFuncAttributeMaxDynamicSharedMemorySize,
                         (int)ATTN_SMEM);
    attn_kernel<<<dim3(S_ / QT, B_), 256, ATTN_SMEM>>>(Qb, Kb, Vb, attn);

    // output projection
    gemm_kernel<<<dim3(D_ / BN, ROWS / BM, 1), 256>>>(attn, wo, wo, wo, ob, ob, ob);

    // residual + LN2
    ln2_kernel<<<ROWS, 256>>>(tokens, ob, g2, b2, out);
}